// round 10
// baseline (speedup 1.0000x reference)
#include <cuda_runtime.h>
#include <cuda_fp16.h>
#include <math.h>

#define NSAMP 32768
#define NFRM  127
#define MPAD  128
#define NB    4
#define WIN   512
#define STEP  256
#define DTRUNC 256
#define PADT  512
#define LPAD  (PADT + NSAMP)

#define NT    128
#define KC    64
#define NCH   (WIN/KC)
#define NCPY  9
#define CSTR  664
#define CLEN  648
#define MTILES (NSAMP/NT)   // 256

#define ABUF  (MPAD*KC*2)
#define SMEM_DYN (2*ABUF + NCPY*CSTR*2 + MPAD*8)

__device__ __align__(16) float g_frames[NB*NFRM*WIN];
__device__ __align__(16) __half g_ah[NB*MPAD*WIN];
__device__ __align__(16) __half g_th[NB*LPAD + 1024];
__device__ unsigned long long g_tkey[NB*NFRM*MTILES];
__device__ float g_Y[NB*NSAMP];
__device__ double g_sum;
__device__ unsigned g_count;

// ---------------- helpers ----------------
__device__ __forceinline__ unsigned smem_u32(const void* p) {
    unsigned a;
    asm("{ .reg .u64 t; cvta.to.shared.u64 t, %1; cvt.u32.u64 %0, t; }" : "=r"(a) : "l"(p));
    return a;
}
__device__ __forceinline__ unsigned encf(float v) {
    unsigned b = __float_as_uint(v);
    return (b & 0x80000000u) ? ~b : (b | 0x80000000u);
}
__device__ __forceinline__ float decf(unsigned e) {
    return (e & 0x80000000u) ? __uint_as_float(e ^ 0x80000000u) : __uint_as_float(~e);
}

#define LDSM_X4(r, addr) \
    asm volatile("ldmatrix.sync.aligned.m8n8.x4.shared.b16 {%0,%1,%2,%3}, [%4];" \
        : "=r"((r)[0]), "=r"((r)[1]), "=r"((r)[2]), "=r"((r)[3]) : "r"(addr))
#define LDSM_X4T(r, addr) \
    asm volatile("ldmatrix.sync.aligned.m8n8.x4.trans.shared.b16 {%0,%1,%2,%3}, [%4];" \
        : "=r"((r)[0]), "=r"((r)[1]), "=r"((r)[2]), "=r"((r)[3]) : "r"(addr))
#define MMA16816H(d, a, b0, b1) \
    asm volatile("mma.sync.aligned.m16n8k16.row.col.f16.f16.f16.f16 " \
        "{%0,%1}, {%2,%3,%4,%5}, {%6,%7}, {%0,%1};" \
        : "+r"((d)[0]), "+r"((d)[1]) \
        : "r"((a)[0]), "r"((a)[1]), "r"((a)[2]), "r"((a)[3]), "r"(b0), "r"(b1))
#define CPASYNC16(dst, src) \
    asm volatile("cp.async.cg.shared.global [%0], [%1], 16;" :: "r"(dst), "l"(src))
#define CPCOMMIT() asm volatile("cp.async.commit_group;" ::: "memory")
#define CPWAIT0()  asm volatile("cp.async.wait_group 0;" ::: "memory")

// ---------------------------------------------------------------------------
// prep
// ---------------------------------------------------------------------------
__global__ void k_prep(const float* __restrict__ recon, const float* __restrict__ target) {
    int i = blockIdx.x * blockDim.x + threadIdx.x;
    if (i < NB*MPAD*WIN) {
        int t = i & (WIN-1);
        int f = (i >> 9) & (MPAD-1);
        int b = i >> 16;
        float v = 0.f;
        if (f < NFRM) {
            float wv = 0.54f - 0.46f * cospif((float)t * (1.0f/256.0f));
            v = wv * recon[b*NSAMP + f*STEP + t];
            g_frames[(b*NFRM + f)*WIN + t] = v;
        }
        g_ah[i] = __float2half(v);
    }
    if (i < NB*LPAD) {
        int b = i / LPAD, j = i - b*LPAD;
        float tv = (j >= PADT) ? target[b*NSAMP + j - PADT] : 0.f;
        g_th[i] = __float2half(tv);
    }
    if (i < 1024) g_th[NB*LPAD + i] = __float2half(0.f);
    if (i < NB*NSAMP) g_Y[i] = 0.f;
    if (i == 0) { g_sum = 0.0; g_count = 0u; }
}

__global__ void k_nop1() {}

// ---------------------------------------------------------------------------
// Stage 1: fp16 mma.sync Toeplitz GEMM (fp16 acc) — UNCHANGED from R9 (48.9us)
// ---------------------------------------------------------------------------
__global__ void __launch_bounds__(256) k_conv_mma() {
    extern __shared__ __align__(16) char dyn[];
    __half* smA = (__half*)dyn;
    __half* smT = (__half*)(dyn + 2*ABUF);
    unsigned long long* red = (unsigned long long*)(dyn + 2*ABUF + NCPY*CSTR*2);

    const int tid = threadIdx.x, lane = tid & 31, warp = tid >> 5;
    const int b = blockIdx.y, m0 = blockIdx.x * NT;
    const int wm = warp & 3, wn = warp >> 2;
    const int mbase = wm*32, nbase = wn*64;
    const int idx = lane & 15, half = lane >> 4;
    const unsigned sA = smem_u32(smA), sT = smem_u32(smT);

    if (tid < MPAD) red[tid] = 0ull;

    unsigned acc[2][8][2];
    #pragma unroll
    for (int mi = 0; mi < 2; ++mi)
        #pragma unroll
        for (int nj = 0; nj < 8; ++nj)
            { acc[mi][nj][0] = 0u; acc[mi][nj][1] = 0u; }

    const int rowA0 = mbase + idx, rowA1 = mbase + 16 + idx;
    const unsigned swz0 = (unsigned)(rowA0 & 7), swz1 = (unsigned)(rowA1 & 7);

    const int c8p = 8 - (idx & 7);
    const unsigned P = sT + (unsigned)(c8p*(CSTR*2))
                     + (unsigned)((512 - idx + nbase + 8*half - c8p) * 2);

    const __half* asrc = g_ah + b*MPAD*WIN;

    {
        #pragma unroll
        for (int r = 0; r < 4; ++r) {
            int i = tid + 256*r;
            int m = i >> 3, u = i & 7;
            CPASYNC16(sA + m*(KC*2) + ((((unsigned)u) ^ (m & 7)) << 4),
                      asrc + m*WIN + u*8);
        }
        CPCOMMIT();
    }
    {
        const __half* tsrc = g_th + b*LPAD + m0;
        #pragma unroll
        for (int c = 1; c < NCPY; ++c)
            for (int i = tid; i < CLEN; i += 256)
                smT[c*CSTR + i] = tsrc[i + c];
    }

    for (int ch = 0; ch < NCH; ++ch) {
        const int cur = ch & 1;
        CPWAIT0();
        __syncthreads();
        if (ch < NCH-1) {
            const __half* src = asrc + (ch+1)*KC;
            const unsigned dstb = sA + (cur ^ 1)*ABUF;
            #pragma unroll
            for (int r = 0; r < 4; ++r) {
                int i = tid + 256*r;
                int m = i >> 3, u = i & 7;
                CPASYNC16(dstb + m*(KC*2) + ((((unsigned)u) ^ (m & 7)) << 4),
                          src + m*WIN + u*8);
            }
            CPCOMMIT();
        }
        const unsigned aB0 = sA + cur*ABUF + rowA0*(KC*2);
        const unsigned aB1 = sA + cur*ABUF + rowA1*(KC*2);
        #pragma unroll
        for (int s = 0; s < 4; ++s) {
            const int S = ch*4 + s;
            unsigned a0[4], a1[4], bb[4][4];
            unsigned u = (unsigned)(2*s + half);
            LDSM_X4(a0, aB0 + ((u ^ swz0) << 4));
            LDSM_X4(a1, aB1 + ((u ^ swz1) << 4));
            unsigned baddr = P - 32u*(unsigned)S;
            LDSM_X4T(bb[0], baddr);
            LDSM_X4T(bb[1], baddr + 32u);
            LDSM_X4T(bb[2], baddr + 64u);
            LDSM_X4T(bb[3], baddr + 96u);
            #pragma unroll
            for (int j = 0; j < 4; ++j) {
                MMA16816H(acc[0][2*j],   a0, bb[j][0], bb[j][1]);
                MMA16816H(acc[0][2*j+1], a0, bb[j][2], bb[j][3]);
                MMA16816H(acc[1][2*j],   a1, bb[j][0], bb[j][1]);
                MMA16816H(acc[1][2*j+1], a1, bb[j][2], bb[j][3]);
            }
        }
    }

    const int c0 = (lane & 3) * 2, r0 = lane >> 2;
    __syncthreads();
    #pragma unroll
    for (int mi = 0; mi < 2; ++mi) {
        #pragma unroll
        for (int q = 0; q < 2; ++q) {
            unsigned long long best = 0ull;
            #pragma unroll
            for (int nj = 0; nj < 8; ++nj) {
                float2 vv = __half22float2(*(const __half2*)&acc[mi][nj][q]);
                unsigned m = (unsigned)(m0 + nbase + 8*nj + c0);
                unsigned long long k0 = ((unsigned long long)encf(vv.x) << 32)
                                      | (unsigned long long)(0xFFFFFFFFu - m);
                unsigned long long k1 = ((unsigned long long)encf(vv.y) << 32)
                                      | (unsigned long long)(0xFFFFFFFFu - (m+1));
                if (k0 > best) best = k0;
                if (k1 > best) best = k1;
            }
            unsigned long long o;
            o = __shfl_xor_sync(0xFFFFFFFFu, best, 1); if (o > best) best = o;
            o = __shfl_xor_sync(0xFFFFFFFFu, best, 2); if (o > best) best = o;
            if ((lane & 3) == 0)
                atomicMax(&red[mbase + 16*mi + 8*q + r0], best);
        }
    }
    __syncthreads();
    if (tid < NFRM)
        g_tkey[(b*NFRM + tid)*MTILES + blockIdx.x] = red[tid];
}

// ---------------------------------------------------------------------------
// Stage 2 + synth, blockDim 512:
//  - tile keys cached in smem for stage B
//  - main conv split: group g=tid>>8 handles taps [256g, 256g+256)
// ---------------------------------------------------------------------------
#define NOUT (WIN + 2*DTRUNC)       // 1024
#define HPAD 512
#define HLEN (HPAD + NOUT)          // 1536

__global__ void __launch_bounds__(512) k_synth(const float* __restrict__ target) {
    __shared__ float hp[HLEN];
    __shared__ float a_s[WIN];
    __shared__ float part[NOUT];
    __shared__ unsigned long long skey[512];
    __shared__ unsigned tkhi[MTILES];
    const int f = blockIdx.x, b = blockIdx.y;
    const int tid = threadIdx.x;

    for (int i = tid; i < WIN; i += 512) a_s[i] = g_frames[(b*NFRM + f)*WIN + i];

    // ---- stage A: approx max over tile keys ----
    const unsigned long long* tk = g_tkey + (b*NFRM + f)*MTILES;
    unsigned long long kv = (tid < MTILES) ? tk[tid] : 0ull;
    if (tid < MTILES) tkhi[tid] = (unsigned)(kv >> 32);
    skey[tid] = kv;
    __syncthreads();
    for (int s = 256; s > 0; s >>= 1) {
        if (tid < s && skey[tid+s] > skey[tid]) skey[tid] = skey[tid+s];
        __syncthreads();
    }
    const float vmax = decf((unsigned)(skey[0] >> 32));
    const unsigned ethr = encf(vmax - 0.05f*fabsf(vmax) - 0.5f);
    __syncthreads();

    // ---- stage B: exact fp32 recompute; lag = tid>>2, tap-quarter = tid&3 ----
    const float* tgt = target + b*NSAMP;
    const int lag = tid >> 2, quart = tid & 3;
    unsigned long long best = 0ull;
    for (int mt = 0; mt < MTILES; ++mt) {
        if (tkhi[mt] < ethr) continue;
        const int m = mt*NT + lag;
        float s = 0.f;
        const int t0 = quart*128;
        #pragma unroll 4
        for (int t = t0; t < t0 + 128; ++t) {
            int x = m - t;
            if (x >= 0) s = fmaf(a_s[t], tgt[x], s);
        }
        s += __shfl_xor_sync(0xFFFFFFFFu, s, 1);
        s += __shfl_xor_sync(0xFFFFFFFFu, s, 2);
        unsigned long long key = ((unsigned long long)encf(s) << 32)
                               | (unsigned long long)(0xFFFFFFFFu - (unsigned)m);
        if (quart == 0 && key > best) best = key;
    }
    skey[tid] = best;
    __syncthreads();
    for (int s = 256; s > 0; s >>= 1) {
        if (tid < s && skey[tid+s] > skey[tid]) skey[tid] = skey[tid+s];
        __syncthreads();
    }
    const int p = (int)(0xFFFFFFFFu - (unsigned)(skey[0] & 0xFFFFFFFFull));

    // ---- h table ----
    const float delta = (float)(2.0 * (double)p / 65538.0);
    const float sd = sinpif(delta);
    for (int i = tid; i < HLEN; i += 512) {
        int k = i - HPAD;
        float h = 0.f;
        if (k >= 0 && k <= 2*DTRUNC) {
            int m = k - DTRUNC;
            if (p == 0) {
                h = (m == 0) ? 1.f : 0.f;
            } else {
                float arg = ((float)m + delta) * (1.0f / 65536.0f);
                float v = sd * (cospif(arg) / sinpif(arg)) * (1.0f / 65536.0f);
                h = (m & 1) ? -v : v;
            }
        }
        hp[i] = h;
    }
    __syncthreads();

    // ---- split-tap shift-register conv ----
    const int g = tid >> 8;            // tap group
    const int xi0 = (tid & 255) * 4;
    const int tbase = g * 256;
    float acc[4], w[4];
    #pragma unroll
    for (int j = 0; j < 4; ++j) { acc[j] = 0.f; w[j] = hp[HPAD + xi0 + j - tbase]; }

    #pragma unroll 16
    for (int t = tbase; t < tbase + 256; ++t) {
        float av = a_s[t];
        #pragma unroll
        for (int j = 3; j >= 1; --j) {
            acc[j] = fmaf(av, w[j], acc[j]);
            w[j] = w[j-1];
        }
        acc[0] = fmaf(av, w[0], acc[0]);
        w[0] = hp[HPAD + xi0 - 1 - t];       // min index: 512 + 0 - 1 - 511 = 0
    }

    if (g == 1) {
        #pragma unroll
        for (int j = 0; j < 4; ++j) part[xi0 + j] = acc[j];
    }
    __syncthreads();
    if (g == 0) {
        #pragma unroll
        for (int j = 0; j < 4; ++j) {
            float v = acc[j] + part[xi0 + j];
            int x = p - DTRUNC + xi0 + j;
            if (x >= 0 && x < NSAMP)
                atomicAdd(&g_Y[b*NSAMP + x], v);
        }
    }
}

// ---------------------------------------------------------------------------
// mse with fused finalize (atomic-counter last block writes out)
// ---------------------------------------------------------------------------
__global__ void k_mse(const float* __restrict__ target, float* __restrict__ out) {
    __shared__ double red[256];
    const int tid = threadIdx.x;
    double s = 0.0;
    for (int i = blockIdx.x*256 + tid; i < NB*NSAMP; i += gridDim.x*256) {
        double d = (double)g_Y[i] - (double)target[i];
        s += d * d;
    }
    red[tid] = s;
    __syncthreads();
    for (int st = 128; st > 0; st >>= 1) {
        if (tid < st) red[tid] += red[tid + st];
        __syncthreads();
    }
    if (tid == 0) {
        atomicAdd(&g_sum, red[0]);
        __threadfence();
        unsigned c = atomicAdd(&g_count, 1u);
        if (c == gridDim.x - 1) {
            out[0] = (float)(g_sum / (double)(NB*NSAMP));
        }
    }
}

extern "C" void kernel_launch(void* const* d_in, const int* in_sizes, int n_in,
                              void* d_out, int out_size) {
    const float* recon  = (const float*)d_in[0];
    const float* target = (const float*)d_in[1];
    float* out = (float*)d_out;
    (void)in_sizes; (void)n_in; (void)out_size;

    cudaFuncSetAttribute(k_conv_mma, cudaFuncAttributeMaxDynamicSharedMemorySize, SMEM_DYN);

    k_prep<<<(NB*MPAD*WIN + 255)/256, 256>>>(recon, target);
    k_conv_mma<<<dim3(MTILES, NB), 256, SMEM_DYN>>>();
    k_nop1<<<1, 32>>>();
    k_synth<<<dim3(NFRM, NB), 512>>>(target);     // capture slot #4
    k_mse<<<256, 256>>>(target, out);
}

// round 11
// speedup vs baseline: 2.3459x; 2.3459x over previous
#include <cuda_runtime.h>
#include <cuda_fp16.h>
#include <math.h>

#define NSAMP 32768
#define NFRM  127
#define MPAD  128
#define NB    4
#define WIN   512
#define STEP  256
#define DTRUNC 256
#define PADT  512
#define LPAD  (PADT + NSAMP)

#define NT    128
#define KC    64
#define NCH   (WIN/KC)
#define NCPY  9
#define CSTR  664
#define CLEN  648
#define MTILES (NSAMP/NT)   // 256

#define ABUF  (MPAD*KC*2)
#define SMEM_DYN (2*ABUF + NCPY*CSTR*2 + MPAD*8)

__device__ __align__(16) float g_frames[NB*NFRM*WIN];
__device__ __align__(16) __half g_ah[NB*MPAD*WIN];
__device__ __align__(16) __half g_th[NB*LPAD + 1024];
__device__ unsigned long long g_tkey[NB*NFRM*MTILES];
__device__ float g_Y[NB*NSAMP];
__device__ double g_sum;
__device__ unsigned g_count;

// ---------------- helpers ----------------
__device__ __forceinline__ unsigned smem_u32(const void* p) {
    unsigned a;
    asm("{ .reg .u64 t; cvta.to.shared.u64 t, %1; cvt.u32.u64 %0, t; }" : "=r"(a) : "l"(p));
    return a;
}
__device__ __forceinline__ unsigned encf(float v) {
    unsigned b = __float_as_uint(v);
    return (b & 0x80000000u) ? ~b : (b | 0x80000000u);
}
__device__ __forceinline__ float decf(unsigned e) {
    return (e & 0x80000000u) ? __uint_as_float(e ^ 0x80000000u) : __uint_as_float(~e);
}

#define LDSM_X4(r, addr) \
    asm volatile("ldmatrix.sync.aligned.m8n8.x4.shared.b16 {%0,%1,%2,%3}, [%4];" \
        : "=r"((r)[0]), "=r"((r)[1]), "=r"((r)[2]), "=r"((r)[3]) : "r"(addr))
#define LDSM_X4T(r, addr) \
    asm volatile("ldmatrix.sync.aligned.m8n8.x4.trans.shared.b16 {%0,%1,%2,%3}, [%4];" \
        : "=r"((r)[0]), "=r"((r)[1]), "=r"((r)[2]), "=r"((r)[3]) : "r"(addr))
#define MMA16816(d, a, b0, b1) \
    asm volatile("mma.sync.aligned.m16n8k16.row.col.f32.f16.f16.f32 " \
        "{%0,%1,%2,%3}, {%4,%5,%6,%7}, {%8,%9}, {%0,%1,%2,%3};" \
        : "+f"((d)[0]), "+f"((d)[1]), "+f"((d)[2]), "+f"((d)[3]) \
        : "r"((a)[0]), "r"((a)[1]), "r"((a)[2]), "r"((a)[3]), "r"(b0), "r"(b1))
#define CPASYNC16(dst, src) \
    asm volatile("cp.async.cg.shared.global [%0], [%1], 16;" :: "r"(dst), "l"(src))
#define CPCOMMIT() asm volatile("cp.async.commit_group;" ::: "memory")
#define CPWAIT0()  asm volatile("cp.async.wait_group 0;" ::: "memory")

// ---------------------------------------------------------------------------
// prep
// ---------------------------------------------------------------------------
__global__ void k_prep(const float* __restrict__ recon, const float* __restrict__ target) {
    int i = blockIdx.x * blockDim.x + threadIdx.x;
    if (i < NB*MPAD*WIN) {
        int t = i & (WIN-1);
        int f = (i >> 9) & (MPAD-1);
        int b = i >> 16;
        float v = 0.f;
        if (f < NFRM) {
            float wv = 0.54f - 0.46f * cospif((float)t * (1.0f/256.0f));
            v = wv * recon[b*NSAMP + f*STEP + t];
            g_frames[(b*NFRM + f)*WIN + t] = v;
        }
        g_ah[i] = __float2half(v);
    }
    if (i < NB*LPAD) {
        int b = i / LPAD, j = i - b*LPAD;
        float tv = (j >= PADT) ? target[b*NSAMP + j - PADT] : 0.f;
        g_th[i] = __float2half(tv);
    }
    if (i < 1024) g_th[NB*LPAD + i] = __float2half(0.f);
    if (i < NB*NSAMP) g_Y[i] = 0.f;
    if (i == 0) { g_sum = 0.0; g_count = 0u; }
}

__global__ void k_nop1() {}

// ---------------------------------------------------------------------------
// Stage 1: fp16-input / fp32-acc mma.sync Toeplitz GEMM.
// cp.async double-buffered A (KC=64); 9-copy conflict-free smT for ldmatrix.
// ---------------------------------------------------------------------------
__global__ void __launch_bounds__(256) k_conv_mma() {
    extern __shared__ __align__(16) char dyn[];
    __half* smA = (__half*)dyn;
    __half* smT = (__half*)(dyn + 2*ABUF);
    unsigned long long* red = (unsigned long long*)(dyn + 2*ABUF + NCPY*CSTR*2);

    const int tid = threadIdx.x, lane = tid & 31, warp = tid >> 5;
    const int b = blockIdx.y, m0 = blockIdx.x * NT;
    const int wm = warp & 3, wn = warp >> 2;
    const int mbase = wm*32, nbase = wn*64;
    const int idx = lane & 15, half = lane >> 4;
    const unsigned sA = smem_u32(smA), sT = smem_u32(smT);

    if (tid < MPAD) red[tid] = 0ull;

    float acc[2][8][4];
    #pragma unroll
    for (int mi = 0; mi < 2; ++mi)
        #pragma unroll
        for (int nj = 0; nj < 8; ++nj)
            #pragma unroll
            for (int e = 0; e < 4; ++e) acc[mi][nj][e] = 0.f;

    const int rowA0 = mbase + idx, rowA1 = mbase + 16 + idx;
    const unsigned swz0 = (unsigned)(rowA0 & 7), swz1 = (unsigned)(rowA1 & 7);

    const int c8p = 8 - (idx & 7);
    const unsigned P = sT + (unsigned)(c8p*(CSTR*2))
                     + (unsigned)((512 - idx + nbase + 8*half - c8p) * 2);

    const __half* asrc = g_ah + b*MPAD*WIN;

    {
        #pragma unroll
        for (int r = 0; r < 4; ++r) {
            int i = tid + 256*r;
            int m = i >> 3, u = i & 7;
            CPASYNC16(sA + m*(KC*2) + ((((unsigned)u) ^ (m & 7)) << 4),
                      asrc + m*WIN + u*8);
        }
        CPCOMMIT();
    }
    {
        const __half* tsrc = g_th + b*LPAD + m0;
        #pragma unroll
        for (int c = 1; c < NCPY; ++c)
            for (int i = tid; i < CLEN; i += 256)
                smT[c*CSTR + i] = tsrc[i + c];
    }

    for (int ch = 0; ch < NCH; ++ch) {
        const int cur = ch & 1;
        CPWAIT0();
        __syncthreads();
        if (ch < NCH-1) {
            const __half* src = asrc + (ch+1)*KC;
            const unsigned dstb = sA + (cur ^ 1)*ABUF;
            #pragma unroll
            for (int r = 0; r < 4; ++r) {
                int i = tid + 256*r;
                int m = i >> 3, u = i & 7;
                CPASYNC16(dstb + m*(KC*2) + ((((unsigned)u) ^ (m & 7)) << 4),
                          src + m*WIN + u*8);
            }
            CPCOMMIT();
        }
        const unsigned aB0 = sA + cur*ABUF + rowA0*(KC*2);
        const unsigned aB1 = sA + cur*ABUF + rowA1*(KC*2);
        #pragma unroll
        for (int s = 0; s < 4; ++s) {
            const int S = ch*4 + s;
            unsigned a0[4], a1[4], bb[4][4];
            unsigned u = (unsigned)(2*s + half);
            LDSM_X4(a0, aB0 + ((u ^ swz0) << 4));
            LDSM_X4(a1, aB1 + ((u ^ swz1) << 4));
            unsigned baddr = P - 32u*(unsigned)S;
            LDSM_X4T(bb[0], baddr);
            LDSM_X4T(bb[1], baddr + 32u);
            LDSM_X4T(bb[2], baddr + 64u);
            LDSM_X4T(bb[3], baddr + 96u);
            #pragma unroll
            for (int j = 0; j < 4; ++j) {
                MMA16816(acc[0][2*j],   a0, bb[j][0], bb[j][1]);
                MMA16816(acc[0][2*j+1], a0, bb[j][2], bb[j][3]);
                MMA16816(acc[1][2*j],   a1, bb[j][0], bb[j][1]);
                MMA16816(acc[1][2*j+1], a1, bb[j][2], bb[j][3]);
            }
        }
    }

    const int c0 = (lane & 3) * 2, r0 = lane >> 2;
    __syncthreads();
    #pragma unroll
    for (int mi = 0; mi < 2; ++mi) {
        #pragma unroll
        for (int q = 0; q < 2; ++q) {
            unsigned long long best = 0ull;
            #pragma unroll
            for (int nj = 0; nj < 8; ++nj) {
                #pragma unroll
                for (int e = 0; e < 2; ++e) {
                    float v = acc[mi][nj][q*2 + e];
                    unsigned m = (unsigned)(m0 + nbase + 8*nj + c0 + e);
                    unsigned long long key = ((unsigned long long)encf(v) << 32)
                                           | (unsigned long long)(0xFFFFFFFFu - m);
                    if (key > best) best = key;
                }
            }
            unsigned long long o;
            o = __shfl_xor_sync(0xFFFFFFFFu, best, 1); if (o > best) best = o;
            o = __shfl_xor_sync(0xFFFFFFFFu, best, 2); if (o > best) best = o;
            if ((lane & 3) == 0)
                atomicMax(&red[mbase + 16*mi + 8*q + r0], best);
        }
    }
    __syncthreads();
    if (tid < NFRM)
        g_tkey[(b*NFRM + tid)*MTILES + blockIdx.x] = red[tid];
}

// ---------------------------------------------------------------------------
// Stage 2 + synth.  Tight slack (fp32-acc stage 1): 0.002|vmax| + 0.05
// -> ~1 qualifying tile.  hp pad-swizzled: phys(i)=i+(i>>5) kills the 4-way
// LDS bank conflict in the tap loop.
// ---------------------------------------------------------------------------
#define NOUT (WIN + 2*DTRUNC)       // 1024
#define R2   (NOUT/256)             // 4
#define HPAD 512
#define HLEN (HPAD + NOUT)          // 1536
#define HPX(i) ((i) + ((i) >> 5))
#define HPLEN (HLEN + HLEN/32)

__global__ void __launch_bounds__(256) k_synth(const float* __restrict__ target) {
    __shared__ float hp[HPLEN];
    __shared__ float a_s[WIN];
    __shared__ unsigned long long skey[256];
    __shared__ unsigned tkhi[MTILES];
    const int f = blockIdx.x, b = blockIdx.y;
    const int tid = threadIdx.x;

    for (int i = tid; i < WIN; i += 256) a_s[i] = g_frames[(b*NFRM + f)*WIN + i];

    // ---- stage A: approx max over tile keys ----
    const unsigned long long* tk = g_tkey + (b*NFRM + f)*MTILES;
    unsigned long long kv = tk[tid];
    tkhi[tid] = (unsigned)(kv >> 32);
    skey[tid] = kv;
    __syncthreads();
    for (int s = 128; s > 0; s >>= 1) {
        if (tid < s && skey[tid+s] > skey[tid]) skey[tid] = skey[tid+s];
        __syncthreads();
    }
    const float vmax = decf((unsigned)(skey[0] >> 32));
    const unsigned ethr = encf(vmax - 0.002f*fabsf(vmax) - 0.05f);
    __syncthreads();

    // ---- stage B: exact fp32 recompute of the (few) qualifying tiles ----
    const float* tgt = target + b*NSAMP;
    const int lag_off = tid >> 1, halfsel = tid & 1;
    unsigned long long best = 0ull;
    for (int mt = 0; mt < MTILES; ++mt) {
        if (tkhi[mt] < ethr) continue;
        const int m = mt*NT + lag_off;
        float s = 0.f;
        const int t0 = halfsel*256;
        #pragma unroll 4
        for (int t = t0; t < t0 + 256; ++t) {
            int x = m - t;
            if (x >= 0) s = fmaf(a_s[t], tgt[x], s);
        }
        float o = __shfl_xor_sync(0xFFFFFFFFu, s, 1);
        float v = s + o;
        unsigned long long key = ((unsigned long long)encf(v) << 32)
                               | (unsigned long long)(0xFFFFFFFFu - (unsigned)m);
        if (halfsel == 0 && key > best) best = key;
    }
    skey[tid] = best;
    __syncthreads();
    for (int s = 128; s > 0; s >>= 1) {
        if (tid < s && skey[tid+s] > skey[tid]) skey[tid] = skey[tid+s];
        __syncthreads();
    }
    const int p = (int)(0xFFFFFFFFu - (unsigned)(skey[0] & 0xFFFFFFFFull));

    // ---- h table (pad-swizzled) ----
    const float delta = (float)(2.0 * (double)p / 65538.0);
    const float sd = sinpif(delta);
    for (int i = tid; i < HLEN; i += 256) {
        int k = i - HPAD;
        float h = 0.f;
        if (k >= 0 && k <= 2*DTRUNC) {
            int m = k - DTRUNC;
            if (p == 0) {
                h = (m == 0) ? 1.f : 0.f;
            } else {
                float arg = ((float)m + delta) * (1.0f / 65536.0f);
                float v = sd * (cospif(arg) / sinpif(arg)) * (1.0f / 65536.0f);
                h = (m & 1) ? -v : v;
            }
        }
        hp[HPX(i)] = h;
    }
    __syncthreads();

    // ---- shift-register conv, conflict-free hp ----
    const int xi0 = tid * R2;
    float acc[R2], w[R2];
    #pragma unroll
    for (int j = 0; j < R2; ++j) { acc[j] = 0.f; w[j] = hp[HPX(HPAD + xi0 + j)]; }

    #pragma unroll 16
    for (int t = 0; t < WIN; ++t) {
        float av = a_s[t];
        #pragma unroll
        for (int j = R2-1; j >= 1; --j) {
            acc[j] = fmaf(av, w[j], acc[j]);
            w[j] = w[j-1];
        }
        acc[0] = fmaf(av, w[0], acc[0]);
        w[0] = hp[HPX(HPAD + xi0 - 1 - t)];
    }

    #pragma unroll
    for (int j = 0; j < R2; ++j) {
        int x = p - DTRUNC + xi0 + j;
        if (x >= 0 && x < NSAMP)
            atomicAdd(&g_Y[b*NSAMP + x], acc[j]);
    }
}

// ---------------------------------------------------------------------------
// mse with fused finalize
// ---------------------------------------------------------------------------
__global__ void k_mse(const float* __restrict__ target, float* __restrict__ out) {
    __shared__ double red[256];
    const int tid = threadIdx.x;
    double s = 0.0;
    for (int i = blockIdx.x*256 + tid; i < NB*NSAMP; i += gridDim.x*256) {
        double d = (double)g_Y[i] - (double)target[i];
        s += d * d;
    }
    red[tid] = s;
    __syncthreads();
    for (int st = 128; st > 0; st >>= 1) {
        if (tid < st) red[tid] += red[tid + st];
        __syncthreads();
    }
    if (tid == 0) {
        atomicAdd(&g_sum, red[0]);
        __threadfence();
        unsigned c = atomicAdd(&g_count, 1u);
        if (c == gridDim.x - 1) {
            out[0] = (float)(g_sum / (double)(NB*NSAMP));
        }
    }
}

extern "C" void kernel_launch(void* const* d_in, const int* in_sizes, int n_in,
                              void* d_out, int out_size) {
    const float* recon  = (const float*)d_in[0];
    const float* target = (const float*)d_in[1];
    float* out = (float*)d_out;
    (void)in_sizes; (void)n_in; (void)out_size;

    cudaFuncSetAttribute(k_conv_mma, cudaFuncAttributeMaxDynamicSharedMemorySize, SMEM_DYN);

    k_prep<<<(NB*MPAD*WIN + 255)/256, 256>>>(recon, target);
    k_conv_mma<<<dim3(MTILES, NB), 256, SMEM_DYN>>>();
    k_nop1<<<1, 32>>>();
    k_synth<<<dim3(NFRM, NB), 256>>>(target);     // capture slot #4
    k_mse<<<256, 256>>>(target, out);
}